// round 11
// baseline (speedup 1.0000x reference)
#include <cuda_runtime.h>
#include <cuda_bf16.h>

#define Hn 512
#define Bn 1024
#define Tn 512
#define On 10
#define NCTA 128

// SMEM byte offsets
#define SM_WHI 0        // 8 chunks x [64 rows x 64 k] bf16 SW128 = 65536
#define SM_WLO 65536
#define SM_A   131072   // 4-buffer ring x 16KB (hi 8K + lo 8K)
#define SM_OWN 196608   // own-chunk buffer, same layout as a ring buffer (16KB)
#define SM_WB  212992   // float2[64] {W_hx, b_h}
#define SM_XS  213504   // float[64]
#define SM_TOTAL 213760

__device__ __align__(16) __nv_bfloat16 g_hhi[2][Hn * Bn];  // [buf][k*Bn + b]
__device__ __align__(16) __nv_bfloat16 g_hlo[2][Hn * Bn];

struct alignas(128) CtBar { unsigned cnt; unsigned gen; unsigned pad[30]; };
__device__ CtBar g_ctbar[16];

static __device__ __forceinline__ unsigned smem_u32(const void* p) {
    unsigned a;
    asm("{ .reg .u64 t; cvta.to.shared.u64 t, %1; cvt.u32.u64 %0, t; }" : "=r"(a) : "l"(p));
    return a;
}
static __device__ __forceinline__ void cpa16(unsigned dst, const void* src) {
    asm volatile("cp.async.cg.shared.global [%0], [%1], 16;" :: "r"(dst), "l"(src));
}
#define CP_COMMIT() asm volatile("cp.async.commit_group;" ::: "memory")
#define CP_WAIT2()  asm volatile("cp.async.wait_group 2;" ::: "memory")
#define CP_WAIT1()  asm volatile("cp.async.wait_group 1;" ::: "memory")
#define CP_WAIT0()  asm volatile("cp.async.wait_group 0;" ::: "memory")

static __device__ __forceinline__ void ldm4(unsigned* r, unsigned addr) {
    asm volatile("ldmatrix.sync.aligned.m8n8.x4.shared.b16 {%0,%1,%2,%3}, [%4];"
                 : "=r"(r[0]), "=r"(r[1]), "=r"(r[2]), "=r"(r[3]) : "r"(addr));
}
static __device__ __forceinline__ void ldm4t(unsigned* r, unsigned addr) {
    asm volatile("ldmatrix.sync.aligned.m8n8.x4.trans.shared.b16 {%0,%1,%2,%3}, [%4];"
                 : "=r"(r[0]), "=r"(r[1]), "=r"(r[2]), "=r"(r[3]) : "r"(addr));
}
static __device__ __forceinline__ void mma16816(float* d, const unsigned* a, const unsigned* b) {
    asm volatile("mma.sync.aligned.m16n8k16.row.col.f32.bf16.bf16.f32 "
                 "{%0,%1,%2,%3}, {%4,%5,%6,%7}, {%8,%9}, {%0,%1,%2,%3};"
                 : "+f"(d[0]), "+f"(d[1]), "+f"(d[2]), "+f"(d[3])
                 : "r"(a[0]), "r"(a[1]), "r"(a[2]), "r"(a[3]), "r"(b[0]), "r"(b[1]));
}

static __device__ __forceinline__ float fast_tanh(float v) {
    float e, r;
    asm("ex2.approx.f32 %0, %1;" : "=f"(e) : "f"(v * 2.885390081777927f));
    asm("rcp.approx.f32 %0, %1;" : "=f"(r) : "f"(e + 1.0f));
    return fmaf(-2.0f, r, 1.0f);
}
static __device__ __forceinline__ unsigned pack_bf2(__nv_bfloat16 a, __nv_bfloat16 b) {
    return (unsigned)__bfloat16_as_ushort(a) | ((unsigned)__bfloat16_as_ushort(b) << 16);
}

// 8-CTA group barrier, full (used once at start).
static __device__ __forceinline__ void ct_barrier(int ct) {
    __syncthreads();
    __threadfence();
    if (threadIdx.x == 0) {
        CtBar* cb = &g_ctbar[ct];
        unsigned gen = *((volatile unsigned*)&cb->gen);
        unsigned tkt = atomicAdd(&cb->cnt, 1u);
        if (tkt == 7u) {
            cb->cnt = 0;
            __threadfence();
            atomicAdd(&cb->gen, 1u);
        } else {
            while (*((volatile unsigned*)&cb->gen) == gen) { __nanosleep(16); }
        }
    }
    __syncthreads();
}

// Split arrive (tid 0 only; caller provides preceding __syncthreads+__threadfence).
// Returns the generation snapshot to wait on.
static __device__ __forceinline__ unsigned ct_arrive(int ct) {
    CtBar* cb = &g_ctbar[ct];
    unsigned g = *((volatile unsigned*)&cb->gen);
    unsigned tkt = atomicAdd(&cb->cnt, 1u);
    if (tkt == 7u) {
        cb->cnt = 0;
        __threadfence();
        atomicAdd(&cb->gen, 1u);
    }
    return g;
}

extern __shared__ char smem[];

__global__ void __launch_bounds__(512, 1)
rnn_hmma8_kernel(const float* __restrict__ x,    const float* __restrict__ W_hx,
                 const float* __restrict__ W_hh, const float* __restrict__ W_yh,
                 const float* __restrict__ b_h,  const float* __restrict__ b_y,
                 float* __restrict__ out)
{
    const unsigned sb = smem_u32(smem);
    const int tid  = threadIdx.x;
    const int lane = tid & 31;
    const int wid  = tid >> 5;
    const int wk   = wid >> 3;           // k half within each chunk
    const int hwid = wid & 7;
    const int nt   = blockIdx.x & 7;     // hidden tile 0..7 (produces chunk nt)
    const int ct   = blockIdx.x >> 3;    // batch group 0..15
    const int n0   = nt * 64;
    const int c0   = ct * 64;
    const int wm   = hwid & 1;
    const int wn   = hwid >> 1;          // 0..3
    const int ks0  = wk * 2;             // this warp's ks base within a chunk

    // ---- Stage W_hh rows n0..n0+63 as bf16 hi/lo: 8 SW128 chunks [64r x 64k] ----
    for (int idx = tid; idx < 64 * Hn; idx += 512) {
        int r = idx >> 9, k = idx & 511;
        float w = W_hh[(n0 + r) * Hn + k];
        __nv_bfloat16 whi = __float2bfloat16(w);
        __nv_bfloat16 wlo = __float2bfloat16(w - __bfloat162float(whi));
        int c = k >> 6, kc = k & 63;
        unsigned off = (unsigned)(r * 128 + kc * 2);
        unsigned sw  = off ^ ((off >> 3) & 0x70);
        *(__nv_bfloat16*)(smem + SM_WHI + c * 8192 + sw) = whi;
        *(__nv_bfloat16*)(smem + SM_WLO + c * 8192 + sw) = wlo;
    }
    if (tid < 64)
        ((float2*)(smem + SM_WB))[tid] = make_float2(W_hx[n0 + tid], b_h[n0 + tid]);

    // ---- Zero own group-aligned region of global buffer 0 ----
    {
        uint4 z = make_uint4(0, 0, 0, 0);
        int r = tid >> 3, q = tid & 7;        // 512 items = 64 rows x 8 uint4
        size_t off = (size_t)(n0 + r) * Bn + c0;
        ((uint4*)(g_hhi[0] + off))[q] = z;
        ((uint4*)(g_hlo[0] + off))[q] = z;
        // zero SM_OWN (1024 uint4)
        ((uint4*)(smem + SM_OWN))[tid]       = z;
        ((uint4*)(smem + SM_OWN))[tid + 512] = z;
    }

    // ---- cp.async slot precompute: 2 x 16B per thread per chunk ----
    const char* s0[2]; const char* s1[2]; unsigned dsw[2];
#pragma unroll
    for (int j = 0; j < 2; ++j) {
        int f = j * 512 + tid;
        int arr = j;                    // 0=hi 1=lo
        int ff = f & 511;
        int row = ff >> 3, seg = ff & 7;
        size_t so = (size_t)row * (Bn * 2) + seg * 16 + (size_t)c0 * 2;
        s0[j] = (const char*)(arr ? g_hlo[0] : g_hhi[0]) + so;
        s1[j] = (const char*)(arr ? g_hlo[1] : g_hhi[1]) + so;
        unsigned off = (unsigned)(row * 128 + seg * 16);
        dsw[j] = (unsigned)(arr * 8192) + (off ^ ((row & 7) << 4));
    }

    // ---- ldmatrix lane constants (verified R4/R10) ----
    const int lane15 = lane & 15;
    const unsigned axor  = (unsigned)((lane & 7) << 4);
    const unsigned arow0 = (unsigned)((wm * 32 + lane15) * 128);
    const unsigned acx   = ((unsigned)((lane >> 4) * 16)) ^ axor;
    const unsigned browb = (unsigned)(lane15 * 128);
    const unsigned bcx   = ((unsigned)(wn * 32 + (lane >> 4) * 16)) ^ axor;

    const float2* WB = (const float2*)(smem + SM_WB);
    float* XS  = (float*)(smem + SM_XS);
    float* RED = (float*)(smem + SM_A);   // reduction scratch (ring bufs 0..)

    ct_barrier(ct);                        // zeros + W staging visible group-wide
    unsigned snap = 0;
    if (tid == 0) snap = ct_arrive(ct);    // pre-loop arrive (pairs with t=0 wait)

#define PFH(i, sp) do {                                                        \
        unsigned db = sb + SM_A + (unsigned)((((i) - 1) & 3) * 16384);         \
        int cc = (nt + (i)) & 7;                                               \
        size_t go = (size_t)cc * 131072;                                       \
        cpa16(db + dsw[0], (sp)[0] + go);                                      \
        cpa16(db + dsw[1], (sp)[1] + go);                                      \
        CP_COMMIT(); } while (0)

#define LDFRAG(s, ksad) do {                                                   \
        unsigned colA = acx ^ (unsigned)((ksad) * 32);                         \
        ldm4(ah[s][0], whb + arow0 + colA);                                    \
        ldm4(ah[s][1], whb + arow0 + 2048 + colA);                             \
        ldm4(al[s][0], wlb + arow0 + colA);                                    \
        ldm4(al[s][1], wlb + arow0 + 2048 + colA);                             \
        unsigned rB = hb + browb + (unsigned)((ksad) * 2048) + bcx;            \
        ldm4t(bh[s], rB);                                                      \
        ldm4t(bl[s], rB + 8192); } while (0)

#define MMAP(s) do {                                                           \
        _Pragma("unroll")                                                      \
        for (int mi = 0; mi < 2; ++mi)                                         \
            _Pragma("unroll")                                                  \
            for (int ni = 0; ni < 2; ++ni) {                                   \
                mma16816(acc[mi][ni], ah[s][mi], bh[s] + ni * 2);              \
                mma16816(acc[mi][ni], ah[s][mi], bl[s] + ni * 2);              \
                mma16816(acc[mi][ni], al[s][mi], bh[s] + ni * 2);              \
            } } while (0)

#define COMPUTE(cidx, hbase) do {                                              \
        const unsigned whb = sb + SM_WHI + (unsigned)((cidx) * 8192);          \
        const unsigned wlb = whb + 65536;                                      \
        const unsigned hb  = (hbase);                                          \
        unsigned ah[2][2][4], al[2][2][4], bh[2][4], bl[2][4];                 \
        LDFRAG(0, ks0);                                                        \
        LDFRAG(1, ks0 + 1);                                                    \
        MMAP(0);                                                               \
        MMAP(1); } while (0)

    for (int t = 0; t < Tn; ++t) {
        float acc[2][2][4];
#pragma unroll
        for (int mi = 0; mi < 2; ++mi)
#pragma unroll
            for (int ni = 0; ni < 2; ++ni)
#pragma unroll
                for (int q = 0; q < 4; ++q) acc[mi][ni][q] = 0.f;

        // Own chunk first — data is in SM_OWN, overlaps the barrier wait.
        COMPUTE(nt, sb + SM_OWN);

        // Wait for the rest of the group to publish h(t).
        if (tid == 0) {
            while (*((volatile unsigned*)&g_ctbar[ct].gen) == snap) { __nanosleep(16); }
        }
        __syncthreads();

        if (tid < 64) XS[tid] = x[(c0 + tid) * Tn + t];
        const char* const* sp = (t & 1) ? s1 : s0;
        PFH(1, sp); PFH(2, sp); PFH(3, sp);

        for (int i = 1; i < 8; ++i) {
            if (i < 6) CP_WAIT2(); else if (i == 6) CP_WAIT1(); else CP_WAIT0();
            __syncthreads();
            COMPUTE((nt + i) & 7, sb + SM_A + (unsigned)(((i - 1) & 3) * 16384));
            if (i < 5) PFH(i + 3, sp);
        }

        // ---- Combine K halves (verified RED machinery) ----
        __syncthreads();
        if (wk == 1) {
#pragma unroll
            for (int mi = 0; mi < 2; ++mi)
#pragma unroll
                for (int ni = 0; ni < 2; ++ni)
#pragma unroll
                    for (int q = 0; q < 4; ++q)
                        RED[(hwid * 16 + (mi * 2 + ni) * 4 + q) * 32 + lane] = acc[mi][ni][q];
        }
        __syncthreads();

        if (wk == 0) {
#pragma unroll
            for (int mi = 0; mi < 2; ++mi)
#pragma unroll
                for (int ni = 0; ni < 2; ++ni)
#pragma unroll
                    for (int q = 0; q < 4; ++q)
                        acc[mi][ni][q] += RED[(hwid * 16 + (mi * 2 + ni) * 4 + q) * 32 + lane];

            // ---- Epilogue: tanh + bf16 hi/lo split; store global + SM_OWN ----
            int ob = (t + 1) & 1;
            __nv_bfloat16* oh = g_hhi[ob];
            __nv_bfloat16* ol = g_hlo[ob];
#pragma unroll
            for (int mi = 0; mi < 2; ++mi) {
                int rA = wm * 32 + mi * 16 + (lane >> 2);
                float2 wA  = WB[rA];
                float2 wB2 = WB[rA + 8];
#pragma unroll
                for (int ni = 0; ni < 2; ++ni) {
                    int bl0 = wn * 16 + ni * 8 + 2 * (lane & 3);
                    float xb0 = XS[bl0], xb1 = XS[bl0 + 1];
                    float* a = acc[mi][ni];
                    float y00 = fast_tanh(fmaf(wA.x,  xb0, a[0] + wA.y));
                    float y01 = fast_tanh(fmaf(wA.x,  xb1, a[1] + wA.y));
                    float y10 = fast_tanh(fmaf(wB2.x, xb0, a[2] + wB2.y));
                    float y11 = fast_tanh(fmaf(wB2.x, xb1, a[3] + wB2.y));
                    __nv_bfloat16 h00 = __float2bfloat16(y00), h01 = __float2bfloat16(y01);
                    __nv_bfloat16 h10 = __float2bfloat16(y10), h11 = __float2bfloat16(y11);
                    unsigned hp0 = pack_bf2(h00, h01);
                    unsigned lp0 = pack_bf2(__float2bfloat16(y00 - __bfloat162float(h00)),
                                            __float2bfloat16(y01 - __bfloat162float(h01)));
                    unsigned hp1 = pack_bf2(h10, h11);
                    unsigned lp1 = pack_bf2(__float2bfloat16(y10 - __bfloat162float(h10)),
                                            __float2bfloat16(y11 - __bfloat162float(h11)));
                    size_t o0 = (size_t)(n0 + rA) * Bn + (c0 + bl0);
                    size_t o1 = o0 + (size_t)8 * Bn;
                    *(unsigned*)(oh + o0) = hp0;
                    *(unsigned*)(ol + o0) = lp0;
                    *(unsigned*)(oh + o1) = hp1;
                    *(unsigned*)(ol + o1) = lp1;
                    // mirror into own-chunk SMEM buffer (chunk layout + swizzle)
                    unsigned offb = (unsigned)(rA * 128 + bl0 * 2);
                    unsigned swz  = offb ^ ((unsigned)(rA & 7) << 4);
                    unsigned offb2 = offb + 1024;          // row rA+8 (same swizzle key)
                    unsigned swz2  = offb2 ^ ((unsigned)(rA & 7) << 4);
                    *(unsigned*)(smem + SM_OWN + swz)         = hp0;
                    *(unsigned*)(smem + SM_OWN + 8192 + swz)  = lp0;
                    *(unsigned*)(smem + SM_OWN + swz2)        = hp1;
                    *(unsigned*)(smem + SM_OWN + 8192 + swz2) = lp1;
                }
            }
        }

        __syncthreads();
        __threadfence();
        if (tid == 0) snap = ct_arrive(ct);   // publish h(t+1); wait at next step top
    }

    // Final wait: group's last h published.
    if (tid == 0) {
        while (*((volatile unsigned*)&g_ctbar[ct].gen) == snap) { __nanosleep(16); }
    }
    __syncthreads();

    // ---- Final projection: out[b][o] = b_y[o] + sum_k W_yh[o][k] * h[k][b] ----
    if (nt == 0) {
        float* Wy = (float*)(smem + SM_WHI);       // main loop done; reuse W region
        for (int idx = tid; idx < On * Hn; idx += 512) Wy[idx] = W_yh[idx];
        __syncthreads();
        if (tid < 64) {
            int b = c0 + tid;
            float a10[On];
#pragma unroll
            for (int o = 0; o < On; ++o) a10[o] = b_y[o];
            const __nv_bfloat16* hh = g_hhi[0];
            const __nv_bfloat16* hl = g_hlo[0];
            for (int k = 0; k < Hn; ++k) {
                float hv = __bfloat162float(hh[(size_t)k * Bn + b])
                         + __bfloat162float(hl[(size_t)k * Bn + b]);
#pragma unroll
                for (int o = 0; o < On; ++o) a10[o] = fmaf(Wy[o * Hn + k], hv, a10[o]);
            }
#pragma unroll
            for (int o = 0; o < On; ++o) out[b * On + o] = a10[o];
        }
    }
}

extern "C" void kernel_launch(void* const* d_in, const int* in_sizes, int n_in,
                              void* d_out, int out_size) {
    (void)in_sizes; (void)n_in; (void)out_size;
    const float* x    = (const float*)d_in[0];
    const float* W_hx = (const float*)d_in[1];
    const float* W_hh = (const float*)d_in[2];
    const float* W_yh = (const float*)d_in[3];
    const float* b_h  = (const float*)d_in[4];
    const float* b_y  = (const float*)d_in[5];
    float* out = (float*)d_out;

    cudaFuncSetAttribute(rnn_hmma8_kernel, cudaFuncAttributeMaxDynamicSharedMemorySize, SM_TOTAL);
    rnn_hmma8_kernel<<<NCTA, 512, SM_TOTAL>>>(x, W_hx, W_hh, W_yh, b_h, b_y, out);
}

// round 12
// speedup vs baseline: 1.2342x; 1.2342x over previous
#include <cuda_runtime.h>
#include <cuda_bf16.h>

#define Hn 512
#define Bn 1024
#define Tn 512
#define On 10
#define NCTA 128

// SMEM byte offsets
#define SM_WHI 0        // 8 chunks x [64 rows x 64 k] bf16 SW128 = 65536
#define SM_WLO 65536
#define SM_A   131072   // 4-buffer ring x 16KB (hi 8K + lo 8K); also RED scratch
#define SM_OWN 196608   // own-chunk buffer, same layout as a ring buffer (16KB)
#define SM_WB  212992   // float2[64] {W_hx, b_h}
#define SM_XS  213504   // float[64]
#define SM_TOTAL 213760

__device__ __align__(16) __nv_bfloat16 g_hhi[2][Hn * Bn];  // [buf][k*Bn + b]
__device__ __align__(16) __nv_bfloat16 g_hlo[2][Hn * Bn];

struct alignas(128) CtBar { unsigned cnt; unsigned gen; unsigned pad[30]; };
__device__ CtBar g_ctbar[16];

static __device__ __forceinline__ unsigned smem_u32(const void* p) {
    unsigned a;
    asm("{ .reg .u64 t; cvta.to.shared.u64 t, %1; cvt.u32.u64 %0, t; }" : "=r"(a) : "l"(p));
    return a;
}
static __device__ __forceinline__ void cpa16(unsigned dst, const void* src) {
    asm volatile("cp.async.cg.shared.global [%0], [%1], 16;" :: "r"(dst), "l"(src));
}
#define CP_COMMIT() asm volatile("cp.async.commit_group;" ::: "memory")
#define CP_WAIT2()  asm volatile("cp.async.wait_group 2;" ::: "memory")
#define CP_WAIT1()  asm volatile("cp.async.wait_group 1;" ::: "memory")
#define CP_WAIT0()  asm volatile("cp.async.wait_group 0;" ::: "memory")

static __device__ __forceinline__ void ldm4(unsigned* r, unsigned addr) {
    asm volatile("ldmatrix.sync.aligned.m8n8.x4.shared.b16 {%0,%1,%2,%3}, [%4];"
                 : "=r"(r[0]), "=r"(r[1]), "=r"(r[2]), "=r"(r[3]) : "r"(addr));
}
static __device__ __forceinline__ void ldm4t(unsigned* r, unsigned addr) {
    asm volatile("ldmatrix.sync.aligned.m8n8.x4.trans.shared.b16 {%0,%1,%2,%3}, [%4];"
                 : "=r"(r[0]), "=r"(r[1]), "=r"(r[2]), "=r"(r[3]) : "r"(addr));
}
static __device__ __forceinline__ void mma16816(float* d, const unsigned* a, const unsigned* b) {
    asm volatile("mma.sync.aligned.m16n8k16.row.col.f32.bf16.bf16.f32 "
                 "{%0,%1,%2,%3}, {%4,%5,%6,%7}, {%8,%9}, {%0,%1,%2,%3};"
                 : "+f"(d[0]), "+f"(d[1]), "+f"(d[2]), "+f"(d[3])
                 : "r"(a[0]), "r"(a[1]), "r"(a[2]), "r"(a[3]), "r"(b[0]), "r"(b[1]));
}

static __device__ __forceinline__ float fast_tanh(float v) {
    float e, r;
    asm("ex2.approx.f32 %0, %1;" : "=f"(e) : "f"(v * 2.885390081777927f));
    asm("rcp.approx.f32 %0, %1;" : "=f"(r) : "f"(e + 1.0f));
    return fmaf(-2.0f, r, 1.0f);
}
static __device__ __forceinline__ unsigned pack_bf2(__nv_bfloat16 a, __nv_bfloat16 b) {
    return (unsigned)__bfloat16_as_ushort(a) | ((unsigned)__bfloat16_as_ushort(b) << 16);
}

// 8-CTA group barrier, full (used once at start).
static __device__ __forceinline__ void ct_barrier(int ct) {
    __syncthreads();
    __threadfence();
    if (threadIdx.x == 0) {
        CtBar* cb = &g_ctbar[ct];
        unsigned gen = *((volatile unsigned*)&cb->gen);
        unsigned tkt = atomicAdd(&cb->cnt, 1u);
        if (tkt == 7u) {
            cb->cnt = 0;
            __threadfence();
            atomicAdd(&cb->gen, 1u);
        } else {
            while (*((volatile unsigned*)&cb->gen) == gen) { __nanosleep(16); }
        }
    }
    __syncthreads();
}

// Split arrive (tid 0 only; caller provides preceding __syncthreads+__threadfence).
static __device__ __forceinline__ unsigned ct_arrive(int ct) {
    CtBar* cb = &g_ctbar[ct];
    unsigned g = *((volatile unsigned*)&cb->gen);
    unsigned tkt = atomicAdd(&cb->cnt, 1u);
    if (tkt == 7u) {
        cb->cnt = 0;
        __threadfence();
        atomicAdd(&cb->gen, 1u);
    }
    return g;
}

extern __shared__ char smem[];

__global__ void __launch_bounds__(512, 1)
rnn_hmma9_kernel(const float* __restrict__ x,    const float* __restrict__ W_hx,
                 const float* __restrict__ W_hh, const float* __restrict__ W_yh,
                 const float* __restrict__ b_h,  const float* __restrict__ b_y,
                 float* __restrict__ out)
{
    const unsigned sb = smem_u32(smem);
    const int tid  = threadIdx.x;
    const int lane = tid & 31;
    const int wid  = tid >> 5;
    // warp grid 2m x 2n x 4k
    const int wk   = wid & 3;            // 16-k slice within each 64-k chunk
    const int wm   = (wid >> 2) & 1;     // 32-row group
    const int wn   = wid >> 3;           // 32-col group
    const int nt   = blockIdx.x & 7;     // hidden tile 0..7 (produces chunk nt)
    const int ct   = blockIdx.x >> 3;    // batch group 0..15
    const int n0   = nt * 64;
    const int c0   = ct * 64;

    // ---- Stage W_hh rows n0..n0+63 as bf16 hi/lo: 8 SW128 chunks [64r x 64k] ----
    for (int idx = tid; idx < 64 * Hn; idx += 512) {
        int r = idx >> 9, k = idx & 511;
        float w = W_hh[(n0 + r) * Hn + k];
        __nv_bfloat16 whi = __float2bfloat16(w);
        __nv_bfloat16 wlo = __float2bfloat16(w - __bfloat162float(whi));
        int c = k >> 6, kc = k & 63;
        unsigned off = (unsigned)(r * 128 + kc * 2);
        unsigned sw  = off ^ ((off >> 3) & 0x70);
        *(__nv_bfloat16*)(smem + SM_WHI + c * 8192 + sw) = whi;
        *(__nv_bfloat16*)(smem + SM_WLO + c * 8192 + sw) = wlo;
    }
    if (tid < 64)
        ((float2*)(smem + SM_WB))[tid] = make_float2(W_hx[n0 + tid], b_h[n0 + tid]);

    // ---- Zero own group-aligned region of global buffer 0 + SM_OWN ----
    {
        uint4 z = make_uint4(0, 0, 0, 0);
        int r = tid >> 3, q = tid & 7;        // 512 items = 64 rows x 8 uint4
        size_t off = (size_t)(n0 + r) * Bn + c0;
        ((uint4*)(g_hhi[0] + off))[q] = z;
        ((uint4*)(g_hlo[0] + off))[q] = z;
        ((uint4*)(smem + SM_OWN))[tid]       = z;
        ((uint4*)(smem + SM_OWN))[tid + 512] = z;
    }

    // ---- cp.async slot precompute: 2 x 16B per thread per chunk ----
    const char* s0[2]; const char* s1[2]; unsigned dsw[2];
#pragma unroll
    for (int j = 0; j < 2; ++j) {
        int arr = j;                    // 0=hi 1=lo
        int ff = tid & 511;
        int row = ff >> 3, seg = ff & 7;
        size_t so = (size_t)row * (Bn * 2) + seg * 16 + (size_t)c0 * 2;
        s0[j] = (const char*)(arr ? g_hlo[0] : g_hhi[0]) + so;
        s1[j] = (const char*)(arr ? g_hlo[1] : g_hhi[1]) + so;
        unsigned off = (unsigned)(row * 128 + seg * 16);
        dsw[j] = (unsigned)(arr * 8192) + (off ^ ((row & 7) << 4));
    }

    // ---- ldmatrix lane constants ----
    const int lane15 = lane & 15;
    const unsigned axor  = (unsigned)((lane & 7) << 4);
    const unsigned arow0 = (unsigned)((wm * 32 + lane15) * 128);
    const unsigned acx   = (((unsigned)((lane >> 4) * 16)) ^ axor) ^ (unsigned)(wk * 32);
    const unsigned browb = (unsigned)(lane15 * 128) + (unsigned)(wk * 2048);
    const unsigned bq    = ((unsigned)(wn * 64 + (lane >> 4) * 16)) ^ axor;

    const float2* WB = (const float2*)(smem + SM_WB);
    float* XS  = (float*)(smem + SM_XS);
    float* RED = (float*)(smem + SM_A);   // reduction scratch (ring bufs, free then)

    ct_barrier(ct);                        // zeros + W staging visible group-wide
    unsigned snap = 0;
    if (tid == 0) snap = ct_arrive(ct);    // pre-loop arrive (pairs with t=0 wait)

#define PFH(i, sp) do {                                                        \
        unsigned db = sb + SM_A + (unsigned)((((i) - 1) & 3) * 16384);         \
        int cc = (nt + (i)) & 7;                                               \
        size_t go = (size_t)cc * 131072;                                       \
        cpa16(db + dsw[0], (sp)[0] + go);                                      \
        cpa16(db + dsw[1], (sp)[1] + go);                                      \
        CP_COMMIT(); } while (0)

#define COMPUTE(cidx, hbase) do {                                              \
        const unsigned whb = sb + SM_WHI + (unsigned)((cidx) * 8192);          \
        const unsigned wlb = whb + 65536;                                      \
        const unsigned hb  = (hbase);                                          \
        unsigned ah[2][4], al[2][4], bh[8], bl[8];                             \
        ldm4(ah[0], whb + arow0 + acx);                                        \
        ldm4(ah[1], whb + arow0 + 2048 + acx);                                 \
        ldm4(al[0], wlb + arow0 + acx);                                        \
        ldm4(al[1], wlb + arow0 + 2048 + acx);                                 \
        unsigned rB = hb + browb;                                              \
        ldm4t(bh,     rB + bq);                                                \
        ldm4t(bh + 4, rB + (bq ^ 32u));                                        \
        ldm4t(bl,     rB + 8192 + bq);                                         \
        ldm4t(bl + 4, rB + 8192 + (bq ^ 32u));                                 \
        _Pragma("unroll")                                                      \
        for (int mi = 0; mi < 2; ++mi)                                         \
            _Pragma("unroll")                                                  \
            for (int ni = 0; ni < 4; ++ni) {                                   \
                mma16816(acc[mi][ni], ah[mi], bh + ni * 2);                    \
                mma16816(acc[mi][ni], ah[mi], bl + ni * 2);                    \
                mma16816(acc[mi][ni], al[mi], bh + ni * 2);                    \
            } } while (0)

    for (int t = 0; t < Tn; ++t) {
        float acc[2][4][4];
#pragma unroll
        for (int mi = 0; mi < 2; ++mi)
#pragma unroll
            for (int ni = 0; ni < 4; ++ni)
#pragma unroll
                for (int q = 0; q < 4; ++q) acc[mi][ni][q] = 0.f;

        // Own chunk first — data in SM_OWN; overlaps the group-barrier wait.
        COMPUTE(nt, sb + SM_OWN);

        // Wait for the rest of the group to publish h(t).
        if (tid == 0) {
            while (*((volatile unsigned*)&g_ctbar[ct].gen) == snap) { __nanosleep(16); }
        }
        __syncthreads();

        if (tid < 64) XS[tid] = x[(c0 + tid) * Tn + t];
        const char* const* sp = (t & 1) ? s1 : s0;
        PFH(1, sp); PFH(2, sp); PFH(3, sp);

        for (int i = 1; i < 8; ++i) {
            if (i < 6) CP_WAIT2(); else if (i == 6) CP_WAIT1(); else CP_WAIT0();
            __syncthreads();
            COMPUTE((nt + i) & 7, sb + SM_A + (unsigned)(((i - 1) & 3) * 16384));
            if (i < 5) PFH(i + 3, sp);
        }

        // ---- Combine 4 k-slices: wk 1..3 store partials, wk 0 accumulates ----
        __syncthreads();
        if (wk != 0) {
            int base = ((wm * 2 + wn) * 3 + (wk - 1)) * 1024;
#pragma unroll
            for (int mi = 0; mi < 2; ++mi)
#pragma unroll
                for (int ni = 0; ni < 4; ++ni)
#pragma unroll
                    for (int q = 0; q < 4; ++q)
                        RED[base + ((mi * 4 + ni) * 4 + q) * 32 + lane] = acc[mi][ni][q];
        }
        __syncthreads();

        if (wk == 0) {
#pragma unroll
            for (int p = 0; p < 3; ++p) {
                int base = ((wm * 2 + wn) * 3 + p) * 1024;
#pragma unroll
                for (int mi = 0; mi < 2; ++mi)
#pragma unroll
                    for (int ni = 0; ni < 4; ++ni)
#pragma unroll
                        for (int q = 0; q < 4; ++q)
                            acc[mi][ni][q] += RED[base + ((mi * 4 + ni) * 4 + q) * 32 + lane];
            }

            // ---- Epilogue: tanh + bf16 hi/lo split; store global + SM_OWN ----
            int ob = (t + 1) & 1;
            __nv_bfloat16* oh = g_hhi[ob];
            __nv_bfloat16* ol = g_hlo[ob];
#pragma unroll
            for (int mi = 0; mi < 2; ++mi) {
                int rA = wm * 32 + mi * 16 + (lane >> 2);
                float2 wA  = WB[rA];
                float2 wB2 = WB[rA + 8];
#pragma unroll
                for (int ni = 0; ni < 4; ++ni) {
                    int bl0 = wn * 32 + ni * 8 + 2 * (lane & 3);
                    float xb0 = XS[bl0], xb1 = XS[bl0 + 1];
                    float* a = acc[mi][ni];
                    float y00 = fast_tanh(fmaf(wA.x,  xb0, a[0] + wA.y));
                    float y01 = fast_tanh(fmaf(wA.x,  xb1, a[1] + wA.y));
                    float y10 = fast_tanh(fmaf(wB2.x, xb0, a[2] + wB2.y));
                    float y11 = fast_tanh(fmaf(wB2.x, xb1, a[3] + wB2.y));
                    __nv_bfloat16 h00 = __float2bfloat16(y00), h01 = __float2bfloat16(y01);
                    __nv_bfloat16 h10 = __float2bfloat16(y10), h11 = __float2bfloat16(y11);
                    unsigned hp0 = pack_bf2(h00, h01);
                    unsigned lp0 = pack_bf2(__float2bfloat16(y00 - __bfloat162float(h00)),
                                            __float2bfloat16(y01 - __bfloat162float(h01)));
                    unsigned hp1 = pack_bf2(h10, h11);
                    unsigned lp1 = pack_bf2(__float2bfloat16(y10 - __bfloat162float(h10)),
                                            __float2bfloat16(y11 - __bfloat162float(h11)));
                    size_t o0 = (size_t)(n0 + rA) * Bn + (c0 + bl0);
                    size_t o1 = o0 + (size_t)8 * Bn;
                    *(unsigned*)(oh + o0) = hp0;
                    *(unsigned*)(ol + o0) = lp0;
                    *(unsigned*)(oh + o1) = hp1;
                    *(unsigned*)(ol + o1) = lp1;
                    // mirror into own-chunk SMEM buffer (chunk layout + swizzle)
                    unsigned offb = (unsigned)(rA * 128 + bl0 * 2);
                    unsigned swz  = offb ^ ((unsigned)(rA & 7) << 4);
                    unsigned offb2 = offb + 1024;          // row rA+8, same key
                    unsigned swz2  = offb2 ^ ((unsigned)(rA & 7) << 4);
                    *(unsigned*)(smem + SM_OWN + swz)         = hp0;
                    *(unsigned*)(smem + SM_OWN + 8192 + swz)  = lp0;
                    *(unsigned*)(smem + SM_OWN + swz2)        = hp1;
                    *(unsigned*)(smem + SM_OWN + 8192 + swz2) = lp1;
                }
            }
        }

        __syncthreads();
        __threadfence();
        if (tid == 0) snap = ct_arrive(ct);   // publish h(t+1); wait at next step top
    }

    // Final wait: group's last h published.
    if (tid == 0) {
        while (*((volatile unsigned*)&g_ctbar[ct].gen) == snap) { __nanosleep(16); }
    }
    __syncthreads();

    // ---- Final projection: out[b][o] = b_y[o] + sum_k W_yh[o][k] * h[k][b] ----
    if (nt == 0) {
        float* Wy = (float*)(smem + SM_WHI);       // main loop done; reuse W region
        for (int idx = tid; idx < On * Hn; idx += 512) Wy[idx] = W_yh[idx];
        __syncthreads();
        if (tid < 64) {
            int b = c0 + tid;
            float a10[On];
#pragma unroll
            for (int o = 0; o < On; ++o) a10[o] = b_y[o];
            const __nv_bfloat16* hh = g_hhi[0];
            const __nv_bfloat16* hl = g_hlo[0];
            for (int k = 0; k < Hn; ++k) {
                float hv = __bfloat162float(hh[(size_t)k * Bn + b])
                         + __bfloat162float(hl[(size_t)k * Bn + b]);
#pragma unroll
                for (int o = 0; o < On; ++o) a10[o] = fmaf(Wy[o * Hn + k], hv, a10[o]);
            }
#pragma unroll
            for (int o = 0; o < On; ++o) out[b * On + o] = a10[o];
        }
    }
}

extern "C" void kernel_launch(void* const* d_in, const int* in_sizes, int n_in,
                              void* d_out, int out_size) {
    (void)in_sizes; (void)n_in; (void)out_size;
    const float* x    = (const float*)d_in[0];
    const float* W_hx = (const float*)d_in[1];
    const float* W_hh = (const float*)d_in[2];
    const float* W_yh = (const float*)d_in[3];
    const float* b_h  = (const float*)d_in[4];
    const float* b_y  = (const float*)d_in[5];
    float* out = (float*)d_out;

    cudaFuncSetAttribute(rnn_hmma9_kernel, cudaFuncAttributeMaxDynamicSharedMemorySize, SM_TOTAL);
    rnn_hmma9_kernel<<<NCTA, 512, SM_TOTAL>>>(x, W_hx, W_hh, W_yh, b_h, b_y, out);
}

// round 14
// speedup vs baseline: 1.5248x; 1.2355x over previous
#include <cuda_runtime.h>
#include <cuda_bf16.h>

#define Hn 512
#define Bn 1024
#define Tn 512
#define On 10
#define NCTA 128

// SMEM byte offsets
#define SM_WHI 0        // 8 chunks x [64 rows x 64 k] bf16 SW128 = 65536
#define SM_WLO 65536
#define SM_A   131072   // 6 bufs x 16KB (hi 8K + lo 8K); half h owns bufs 3h..3h+2
#define SM_WB  229376   // float2[64] {W_hx, b_h}
#define SM_XS  229888   // float[64]
#define SM_TOTAL 230144

__device__ __align__(16) __nv_bfloat16 g_hhi[2][Hn * Bn];  // [buf][k*Bn + b]
__device__ __align__(16) __nv_bfloat16 g_hlo[2][Hn * Bn];

struct alignas(128) CtBar { unsigned cnt; unsigned gen; unsigned pad[30]; };
__device__ CtBar g_ctbar[16];

static __device__ __forceinline__ unsigned smem_u32(const void* p) {
    unsigned a;
    asm("{ .reg .u64 t; cvta.to.shared.u64 t, %1; cvt.u32.u64 %0, t; }" : "=r"(a) : "l"(p));
    return a;
}
static __device__ __forceinline__ void cpa16(unsigned dst, const void* src) {
    asm volatile("cp.async.cg.shared.global [%0], [%1], 16;" :: "r"(dst), "l"(src));
}
#define CP_COMMIT() asm volatile("cp.async.commit_group;" ::: "memory")
#define CP_WAIT1()  asm volatile("cp.async.wait_group 1;" ::: "memory")
#define CP_WAIT0()  asm volatile("cp.async.wait_group 0;" ::: "memory")

static __device__ __forceinline__ void ldm4(unsigned* r, unsigned addr) {
    asm volatile("ldmatrix.sync.aligned.m8n8.x4.shared.b16 {%0,%1,%2,%3}, [%4];"
                 : "=r"(r[0]), "=r"(r[1]), "=r"(r[2]), "=r"(r[3]) : "r"(addr));
}
static __device__ __forceinline__ void ldm4t(unsigned* r, unsigned addr) {
    asm volatile("ldmatrix.sync.aligned.m8n8.x4.trans.shared.b16 {%0,%1,%2,%3}, [%4];"
                 : "=r"(r[0]), "=r"(r[1]), "=r"(r[2]), "=r"(r[3]) : "r"(addr));
}
static __device__ __forceinline__ void mma16816(float* d, const unsigned* a, const unsigned* b) {
    asm volatile("mma.sync.aligned.m16n8k16.row.col.f32.bf16.bf16.f32 "
                 "{%0,%1,%2,%3}, {%4,%5,%6,%7}, {%8,%9}, {%0,%1,%2,%3};"
                 : "+f"(d[0]), "+f"(d[1]), "+f"(d[2]), "+f"(d[3])
                 : "r"(a[0]), "r"(a[1]), "r"(a[2]), "r"(a[3]), "r"(b[0]), "r"(b[1]));
}

static __device__ __forceinline__ float fast_tanh(float v) {
    float e, r;
    asm("ex2.approx.f32 %0, %1;" : "=f"(e) : "f"(v * 2.885390081777927f));
    asm("rcp.approx.f32 %0, %1;" : "=f"(r) : "f"(e + 1.0f));
    return fmaf(-2.0f, r, 1.0f);
}
static __device__ __forceinline__ unsigned pack_bf2(__nv_bfloat16 a, __nv_bfloat16 b) {
    return (unsigned)__bfloat16_as_ushort(a) | ((unsigned)__bfloat16_as_ushort(b) << 16);
}

// Per-half named barrier: id 1 (half 0) / id 2 (half 1), 256 threads each.
static __device__ __forceinline__ void half_bar(int half) {
    asm volatile("bar.sync %0, 256;" :: "r"(1 + half) : "memory");
}

// 8-CTA barrier over the CTAs sharing one ct group.
static __device__ __forceinline__ void ct_barrier(int ct) {
    __syncthreads();
    __threadfence();
    if (threadIdx.x == 0) {
        CtBar* cb = &g_ctbar[ct];
        unsigned gen = *((volatile unsigned*)&cb->gen);
        unsigned tkt = atomicAdd(&cb->cnt, 1u);
        if (tkt == 7u) {
            cb->cnt = 0;
            __threadfence();
            atomicAdd(&cb->gen, 1u);
        } else {
            while (*((volatile unsigned*)&cb->gen) == gen) { __nanosleep(16); }
        }
    }
    __syncthreads();
}

extern __shared__ char smem[];

__global__ void __launch_bounds__(512, 1)
rnn_hmma10_kernel(const float* __restrict__ x,    const float* __restrict__ W_hx,
                  const float* __restrict__ W_hh, const float* __restrict__ W_yh,
                  const float* __restrict__ b_h,  const float* __restrict__ b_y,
                  float* __restrict__ out)
{
    const unsigned sb = smem_u32(smem);
    const int tid  = threadIdx.x;
    const int lane = tid & 31;
    const int wid  = tid >> 5;
    const int half = wid >> 3;           // K half: 0 -> chunks 0..3, 1 -> chunks 4..7
    const int hwid = wid & 7;            // warp id within half (R10 roles)
    const int htid = tid & 255;          // thread id within half
    const int nt   = blockIdx.x & 7;     // hidden tile 0..7
    const int ct   = blockIdx.x >> 3;    // batch group 0..15
    const int n0   = nt * 64;
    const int c0   = ct * 64;
    const int wm   = hwid & 1;
    const int wn   = hwid >> 1;          // 0..3

    // ---- Stage W_hh rows n0..n0+63 as bf16 hi/lo: 8 SW128 chunks [64r x 64k] ----
    for (int idx = tid; idx < 64 * Hn; idx += 512) {
        int r = idx >> 9, k = idx & 511;
        float w = W_hh[(n0 + r) * Hn + k];
        __nv_bfloat16 whi = __float2bfloat16(w);
        __nv_bfloat16 wlo = __float2bfloat16(w - __bfloat162float(whi));
        int c = k >> 6, kc = k & 63;
        unsigned off = (unsigned)(r * 128 + kc * 2);
        unsigned sw  = off ^ ((off >> 3) & 0x70);
        *(__nv_bfloat16*)(smem + SM_WHI + c * 8192 + sw) = whi;
        *(__nv_bfloat16*)(smem + SM_WLO + c * 8192 + sw) = wlo;
    }
    if (tid < 64)
        ((float2*)(smem + SM_WB))[tid] = make_float2(W_hx[n0 + tid], b_h[n0 + tid]);

    // ---- Zero own group-aligned region of buffer 0 ----
    {
        uint4 z = make_uint4(0, 0, 0, 0);
        int r = tid >> 3, q = tid & 7;        // 512 items = 64 rows x 8 uint4
        size_t off = (size_t)(n0 + r) * Bn + c0;
        ((uint4*)(g_hhi[0] + off))[q] = z;
        ((uint4*)(g_hlo[0] + off))[q] = z;
    }

    // ---- cp.async slot precompute: 4 x 16B per HALF-thread per chunk ----
    const char* s0[4]; const char* s1[4]; unsigned dsw[4];
#pragma unroll
    for (int j = 0; j < 4; ++j) {
        int f = j * 256 + htid;
        int arr = f >> 9;               // 0=hi 1=lo
        int ff = f & 511;
        int row = ff >> 3, seg = ff & 7;
        size_t so = (size_t)row * (Bn * 2) + seg * 16 + (size_t)c0 * 2;
        s0[j] = (const char*)g_hhi[0] + so;
        if (arr) s0[j] = (const char*)g_hlo[0] + so;
        s1[j] = (const char*)g_hhi[1] + so;
        if (arr) s1[j] = (const char*)g_hlo[1] + so;
        unsigned off = (unsigned)(row * 128 + seg * 16);
        dsw[j] = (unsigned)(arr * 8192) + (off ^ ((row & 7) << 4));
    }

    // ---- ldmatrix lane constants (identical to R4/R10) ----
    const int lane15 = lane & 15;
    const unsigned axor  = (unsigned)((lane & 7) << 4);
    const unsigned arow0 = (unsigned)((wm * 32 + lane15) * 128);
    const unsigned acx   = ((unsigned)((lane >> 4) * 16)) ^ axor;
    const unsigned browb = (unsigned)(lane15 * 128);
    const unsigned bcx   = ((unsigned)(wn * 32 + (lane >> 4) * 16)) ^ axor;

    const float2* WB = (const float2*)(smem + SM_WB);
    float* XS  = (float*)(smem + SM_XS);
    float* RED = (float*)(smem + SM_A);   // reduction scratch (bufs idle then)

    const int cbase = half * 4;           // first global chunk of this half
    const unsigned bufb = (unsigned)(half * 3);

    ct_barrier(ct);   // h0 zeros (group-local) + W staging visible

    // buf index for chunk i (0..3): (i % 3)
#define PFH(i, sp) do {                                                        \
        unsigned db = sb + SM_A + (bufb + (unsigned)((i) % 3)) * 16384u;       \
        size_t go = (size_t)(cbase + (i)) * 131072;                            \
        cpa16(db + dsw[0], (sp)[0] + go);                                      \
        cpa16(db + dsw[1], (sp)[1] + go);                                      \
        cpa16(db + dsw[2], (sp)[2] + go);                                      \
        cpa16(db + dsw[3], (sp)[3] + go);                                      \
        CP_COMMIT(); } while (0)

#define LDFRAG(s, ks) do {                                                     \
        unsigned colA = acx ^ (unsigned)((ks) * 32);                           \
        ldm4(ah[s][0], whb + arow0 + colA);                                    \
        ldm4(ah[s][1], whb + arow0 + 2048 + colA);                             \
        ldm4(al[s][0], wlb + arow0 + colA);                                    \
        ldm4(al[s][1], wlb + arow0 + 2048 + colA);                             \
        unsigned rB = hb + browb + (unsigned)((ks) * 2048) + bcx;              \
        ldm4t(bh[s], rB);                                                      \
        ldm4t(bl[s], rB + 8192); } while (0)

    for (int t = 0; t < Tn; ++t) {
        if (tid < 64) XS[tid] = x[(c0 + tid) * Tn + t];
        const char* const* sp = (t & 1) ? s1 : s0;
        PFH(0, sp);
        PFH(1, sp);

        float acc[2][2][4];
#pragma unroll
        for (int mi = 0; mi < 2; ++mi)
#pragma unroll
            for (int ni = 0; ni < 2; ++ni)
#pragma unroll
                for (int q = 0; q < 4; ++q) acc[mi][ni][q] = 0.f;

        for (int i = 0; i < 4; ++i) {
            if (i < 3) CP_WAIT1(); else CP_WAIT0();
            half_bar(half);               // single bar: data visible; old reads done

            const int c = cbase + i;
            const unsigned whb = sb + SM_WHI + (unsigned)(c * 8192);
            const unsigned wlb = whb + 65536;
            const unsigned hb  = sb + SM_A + (bufb + (unsigned)(i % 3)) * 16384u;

            unsigned ah[2][2][4], al[2][2][4], bh[2][4], bl[2][4];
            LDFRAG(0, 0);
#pragma unroll
            for (int ks = 0; ks < 4; ++ks) {
                const int s = ks & 1;
                if (ks < 3) LDFRAG(s ^ 1, ks + 1);
#pragma unroll
                for (int mi = 0; mi < 2; ++mi)
#pragma unroll
                    for (int ni = 0; ni < 2; ++ni) {
                        mma16816(acc[mi][ni], ah[s][mi], bh[s] + ni * 2);
                        mma16816(acc[mi][ni], ah[s][mi], bl[s] + ni * 2);
                        mma16816(acc[mi][ni], al[s][mi], bh[s] + ni * 2);
                    }
            }
            if (i < 2) PFH(i + 2, sp);    // buf (i+2)%3: last read 3 bars ago
        }

        // ---- Combine K halves: half 1 stores partials, half 0 accumulates ----
        __syncthreads();
        if (half == 1) {
#pragma unroll
            for (int mi = 0; mi < 2; ++mi)
#pragma unroll
                for (int ni = 0; ni < 2; ++ni)
#pragma unroll
                    for (int q = 0; q < 4; ++q)
                        RED[(hwid * 16 + (mi * 2 + ni) * 4 + q) * 32 + lane] = acc[mi][ni][q];
        }
        __syncthreads();

        if (half == 0) {
#pragma unroll
            for (int mi = 0; mi < 2; ++mi)
#pragma unroll
                for (int ni = 0; ni < 2; ++ni)
#pragma unroll
                    for (int q = 0; q < 4; ++q)
                        acc[mi][ni][q] += RED[(hwid * 16 + (mi * 2 + ni) * 4 + q) * 32 + lane];

            // ---- Epilogue: tanh + bf16 hi/lo split + store to ping-pong buffer ----
            int ob = (t + 1) & 1;
            __nv_bfloat16* oh = g_hhi[ob];
            __nv_bfloat16* ol = g_hlo[ob];
#pragma unroll
            for (int mi = 0; mi < 2; ++mi) {
                int rA = wm * 32 + mi * 16 + (lane >> 2);
                float2 wA  = WB[rA];
                float2 wB2 = WB[rA + 8];
#pragma unroll
                for (int ni = 0; ni < 2; ++ni) {
                    int bl0 = wn * 16 + ni * 8 + 2 * (lane & 3);
                    float xb0 = XS[bl0], xb1 = XS[bl0 + 1];
                    float* a = acc[mi][ni];
                    float y00 = fast_tanh(fmaf(wA.x,  xb0, a[0] + wA.y));
                    float y01 = fast_tanh(fmaf(wA.x,  xb1, a[1] + wA.y));
                    float y10 = fast_tanh(fmaf(wB2.x, xb0, a[2] + wB2.y));
                    float y11 = fast_tanh(fmaf(wB2.x, xb1, a[3] + wB2.y));
                    __nv_bfloat16 h00 = __float2bfloat16(y00), h01 = __float2bfloat16(y01);
                    __nv_bfloat16 h10 = __float2bfloat16(y10), h11 = __float2bfloat16(y11);
                    size_t o0 = (size_t)(n0 + rA) * Bn + (c0 + bl0);
                    size_t o1 = o0 + (size_t)8 * Bn;
                    *(unsigned*)(oh + o0) = pack_bf2(h00, h01);
                    *(unsigned*)(ol + o0) = pack_bf2(__float2bfloat16(y00 - __bfloat162float(h00)),
                                                     __float2bfloat16(y01 - __bfloat162float(h01)));
                    *(unsigned*)(oh + o1) = pack_bf2(h10, h11);
                    *(unsigned*)(ol + o1) = pack_bf2(__float2bfloat16(y10 - __bfloat162float(h10)),
                                                     __float2bfloat16(y11 - __bfloat162float(h11)));
                }
            }
        }
        ct_barrier(ct);   // publishes this step's h within the 8-CTA group
    }

    // ---- Final projection: out[b][o] = b_y[o] + sum_k W_yh[o][k] * h[k][b] ----
    if (nt == 0) {
        float* Wy = (float*)(smem + SM_WHI);       // main loop done; reuse W region
        for (int idx = tid; idx < On * Hn; idx += 512) Wy[idx] = W_yh[idx];
        __syncthreads();
        if (tid < 64) {
            int b = c0 + tid;
            float a10[On];
#pragma unroll
            for (int o = 0; o < On; ++o) a10[o] = b_y[o];
            const __nv_bfloat16* hh = g_hhi[0];
            const __nv_bfloat16* hl = g_hlo[0];
            for (int k = 0; k < Hn; ++k) {
                float hv = __bfloat162float(hh[(size_t)k * Bn + b])
                         + __bfloat162float(hl[(size_t)k * Bn + b]);
#pragma unroll
                for (int o = 0; o < On; ++o) a10[o] = fmaf(Wy[o * Hn + k], hv, a10[o]);
            }
#pragma unroll
            for (int o = 0; o < On; ++o) out[b * On + o] = a10[o];
        }
    }
}

extern "C" void kernel_launch(void* const* d_in, const int* in_sizes, int n_in,
                              void* d_out, int out_size) {
    (void)in_sizes; (void)n_in; (void)out_size;
    const float* x    = (const float*)d_in[0];
    const float* W_hx = (const float*)d_in[1];
    const float* W_hh = (const float*)d_in[2];
    const float* W_yh = (const float*)d_in[3];
    const float* b_h  = (const float*)d_in[4];
    const float* b_y  = (const float*)d_in[5];
    float* out = (float*)d_out;

    cudaFuncSetAttribute(rnn_hmma10_kernel, cudaFuncAttributeMaxDynamicSharedMemorySize, SM_TOTAL);
    rnn_hmma10_kernel<<<NCTA, 512, SM_TOTAL>>>(x, W_hx, W_hh, W_yh, b_h, b_y, out);
}

// round 15
// speedup vs baseline: 1.8229x; 1.1955x over previous
#include <cuda_runtime.h>
#include <cuda_fp16.h>

#define Hn 512
#define Bn 1024
#define Tn 512
#define On 10
#define NCTA 128

// SMEM byte offsets
#define SM_WHI 0        // 8 chunks x [64 rows x 64 k] fp16 SW128 = 65536
#define SM_WLO 65536    // fp16 residual of W
#define SM_A   131072   // 6 bufs x 8KB (h fp16); half h owns bufs 3h..3h+2
#define SM_WB  180224   // float2[64] {W_hx, b_h}
#define SM_XS  180736   // float[64]
#define SM_TOTAL 180992

__device__ __align__(16) __half g_h[2][Hn * Bn];   // [buf][k*Bn + b], single fp16

struct alignas(128) CtBar { unsigned cnt; unsigned gen; unsigned pad[30]; };
__device__ CtBar g_ctbar[16];

static __device__ __forceinline__ unsigned smem_u32(const void* p) {
    unsigned a;
    asm("{ .reg .u64 t; cvta.to.shared.u64 t, %1; cvt.u32.u64 %0, t; }" : "=r"(a) : "l"(p));
    return a;
}
static __device__ __forceinline__ void cpa16(unsigned dst, const void* src) {
    asm volatile("cp.async.cg.shared.global [%0], [%1], 16;" :: "r"(dst), "l"(src));
}
#define CP_COMMIT() asm volatile("cp.async.commit_group;" ::: "memory")
#define CP_WAIT1()  asm volatile("cp.async.wait_group 1;" ::: "memory")
#define CP_WAIT0()  asm volatile("cp.async.wait_group 0;" ::: "memory")

static __device__ __forceinline__ void ldm4(unsigned* r, unsigned addr) {
    asm volatile("ldmatrix.sync.aligned.m8n8.x4.shared.b16 {%0,%1,%2,%3}, [%4];"
                 : "=r"(r[0]), "=r"(r[1]), "=r"(r[2]), "=r"(r[3]) : "r"(addr));
}
static __device__ __forceinline__ void ldm4t(unsigned* r, unsigned addr) {
    asm volatile("ldmatrix.sync.aligned.m8n8.x4.trans.shared.b16 {%0,%1,%2,%3}, [%4];"
                 : "=r"(r[0]), "=r"(r[1]), "=r"(r[2]), "=r"(r[3]) : "r"(addr));
}
static __device__ __forceinline__ void mma16816(float* d, const unsigned* a, const unsigned* b) {
    asm volatile("mma.sync.aligned.m16n8k16.row.col.f32.f16.f16.f32 "
                 "{%0,%1,%2,%3}, {%4,%5,%6,%7}, {%8,%9}, {%0,%1,%2,%3};"
                 : "+f"(d[0]), "+f"(d[1]), "+f"(d[2]), "+f"(d[3])
                 : "r"(a[0]), "r"(a[1]), "r"(a[2]), "r"(a[3]), "r"(b[0]), "r"(b[1]));
}

static __device__ __forceinline__ float fast_tanh(float v) {
    float e, r;
    asm("ex2.approx.f32 %0, %1;" : "=f"(e) : "f"(v * 2.885390081777927f));
    asm("rcp.approx.f32 %0, %1;" : "=f"(r) : "f"(e + 1.0f));
    return fmaf(-2.0f, r, 1.0f);
}
static __device__ __forceinline__ unsigned pack_h2(__half a, __half b) {
    return (unsigned)__half_as_ushort(a) | ((unsigned)__half_as_ushort(b) << 16);
}

// Per-half named barrier: id 1 (half 0) / id 2 (half 1), 256 threads each.
static __device__ __forceinline__ void half_bar(int half) {
    asm volatile("bar.sync %0, 256;" :: "r"(1 + half) : "memory");
}

// 8-CTA barrier over the CTAs sharing one ct group.
static __device__ __forceinline__ void ct_barrier(int ct) {
    __syncthreads();
    __threadfence();
    if (threadIdx.x == 0) {
        CtBar* cb = &g_ctbar[ct];
        unsigned gen = *((volatile unsigned*)&cb->gen);
        unsigned tkt = atomicAdd(&cb->cnt, 1u);
        if (tkt == 7u) {
            cb->cnt = 0;
            __threadfence();
            atomicAdd(&cb->gen, 1u);
        } else {
            while (*((volatile unsigned*)&cb->gen) == gen) { __nanosleep(16); }
        }
    }
    __syncthreads();
}

extern __shared__ char smem[];

__global__ void __launch_bounds__(512, 1)
rnn_hmma11_kernel(const float* __restrict__ x,    const float* __restrict__ W_hx,
                  const float* __restrict__ W_hh, const float* __restrict__ W_yh,
                  const float* __restrict__ b_h,  const float* __restrict__ b_y,
                  float* __restrict__ out)
{
    const unsigned sb = smem_u32(smem);
    const int tid  = threadIdx.x;
    const int lane = tid & 31;
    const int wid  = tid >> 5;
    const int half = wid >> 3;           // K half: 0 -> chunks 0..3, 1 -> chunks 4..7
    const int hwid = wid & 7;            // warp id within half
    const int htid = tid & 255;          // thread id within half
    const int nt   = blockIdx.x & 7;     // hidden tile 0..7
    const int ct   = blockIdx.x >> 3;    // batch group 0..15
    const int n0   = nt * 64;
    const int c0   = ct * 64;
    const int wm   = hwid & 1;
    const int wn   = hwid >> 1;          // 0..3

    // ---- Stage W_hh rows n0..n0+63 as fp16 hi/lo: 8 SW128 chunks [64r x 64k] ----
    for (int idx = tid; idx < 64 * Hn; idx += 512) {
        int r = idx >> 9, k = idx & 511;
        float w = W_hh[(n0 + r) * Hn + k];
        __half whi = __float2half_rn(w);
        __half wlo = __float2half_rn(w - __half2float(whi));
        int c = k >> 6, kc = k & 63;
        unsigned off = (unsigned)(r * 128 + kc * 2);
        unsigned sw  = off ^ ((off >> 3) & 0x70);
        *(__half*)(smem + SM_WHI + c * 8192 + sw) = whi;
        *(__half*)(smem + SM_WLO + c * 8192 + sw) = wlo;
    }
    if (tid < 64)
        ((float2*)(smem + SM_WB))[tid] = make_float2(W_hx[n0 + tid], b_h[n0 + tid]);

    // ---- Zero own group-aligned region of buffer 0 ----
    {
        uint4 z = make_uint4(0, 0, 0, 0);
        int r = tid >> 3, q = tid & 7;        // 512 items = 64 rows x 8 uint4
        size_t off = (size_t)(n0 + r) * Bn + c0;
        ((uint4*)(g_h[0] + off))[q] = z;
    }

    // ---- cp.async slot precompute: 2 x 16B per HALF-thread per chunk (8KB) ----
    const char* s0[2]; const char* s1[2]; unsigned dsw[2];
#pragma unroll
    for (int j = 0; j < 2; ++j) {
        int f = j * 256 + htid;          // 0..511
        int row = f >> 3, seg = f & 7;
        size_t so = (size_t)row * (Bn * 2) + seg * 16 + (size_t)c0 * 2;
        s0[j] = (const char*)g_h[0] + so;
        s1[j] = (const char*)g_h[1] + so;
        unsigned off = (unsigned)(row * 128 + seg * 16);
        dsw[j] = off ^ ((row & 7) << 4);
    }

    // ---- ldmatrix lane constants (identical to R4/R10/R14) ----
    const int lane15 = lane & 15;
    const unsigned axor  = (unsigned)((lane & 7) << 4);
    const unsigned arow0 = (unsigned)((wm * 32 + lane15) * 128);
    const unsigned acx   = ((unsigned)((lane >> 4) * 16)) ^ axor;
    const unsigned browb = (unsigned)(lane15 * 128);
    const unsigned bcx   = ((unsigned)(wn * 32 + (lane >> 4) * 16)) ^ axor;

    const float2* WB = (const float2*)(smem + SM_WB);
    float* XS  = (float*)(smem + SM_XS);
    float* RED = (float*)(smem + SM_A);   // reduction scratch (bufs idle then)

    const int cbase = half * 4;           // first global chunk of this half
    const unsigned bufb = (unsigned)(half * 3);

    ct_barrier(ct);   // h0 zeros (group-local) + W staging visible

#define PFH(i, sp) do {                                                        \
        unsigned db = sb + SM_A + (bufb + (unsigned)((i) % 3)) * 8192u;        \
        size_t go = (size_t)(cbase + (i)) * 131072;                            \
        cpa16(db + dsw[0], (sp)[0] + go);                                      \
        cpa16(db + dsw[1], (sp)[1] + go);                                      \
        CP_COMMIT(); } while (0)

#define LDFRAG(s, ks) do {                                                     \
        unsigned colA = acx ^ (unsigned)((ks) * 32);                           \
        ldm4(ah[s][0], whb + arow0 + colA);                                    \
        ldm4(ah[s][1], whb + arow0 + 2048 + colA);                             \
        ldm4(al[s][0], wlb + arow0 + colA);                                    \
        ldm4(al[s][1], wlb + arow0 + 2048 + colA);                             \
        unsigned rB = hb + browb + (unsigned)((ks) * 2048) + bcx;              \
        ldm4t(bh[s], rB); } while (0)

    for (int t = 0; t < Tn; ++t) {
        if (tid < 64) XS[tid] = x[(c0 + tid) * Tn + t];
        const char* const* sp = (t & 1) ? s1 : s0;
        PFH(0, sp);
        PFH(1, sp);

        float acc[2][2][4];
#pragma unroll
        for (int mi = 0; mi < 2; ++mi)
#pragma unroll
            for (int ni = 0; ni < 2; ++ni)
#pragma unroll
                for (int q = 0; q < 4; ++q) acc[mi][ni][q] = 0.f;

        for (int i = 0; i < 4; ++i) {
            if (i < 3) CP_WAIT1(); else CP_WAIT0();
            half_bar(half);               // data visible; prior ring reads done

            const int c = cbase + i;
            const unsigned whb = sb + SM_WHI + (unsigned)(c * 8192);
            const unsigned wlb = whb + 65536;
            const unsigned hb  = sb + SM_A + (bufb + (unsigned)(i % 3)) * 8192u;

            unsigned ah[2][2][4], al[2][2][4], bh[2][4];
            LDFRAG(0, 0);
#pragma unroll
            for (int ks = 0; ks < 4; ++ks) {
                const int s = ks & 1;
                if (ks < 3) LDFRAG(s ^ 1, ks + 1);
#pragma unroll
                for (int mi = 0; mi < 2; ++mi)
#pragma unroll
                    for (int ni = 0; ni < 2; ++ni) {
                        mma16816(acc[mi][ni], ah[s][mi], bh[s] + ni * 2);
                        mma16816(acc[mi][ni], al[s][mi], bh[s] + ni * 2);
                    }
            }
            if (i < 2) PFH(i + 2, sp);    // buf (i+2)%3: last read 3 bars ago
        }

        // ---- Combine K halves: half 1 stores partials, half 0 accumulates ----
        __syncthreads();
        if (half == 1) {
#pragma unroll
            for (int mi = 0; mi < 2; ++mi)
#pragma unroll
                for (int ni = 0; ni < 2; ++ni)
#pragma unroll
                    for (int q = 0; q < 4; ++q)
                        RED[(hwid * 16 + (mi * 2 + ni) * 4 + q) * 32 + lane] = acc[mi][ni][q];
        }
        __syncthreads();

        if (half == 0) {
#pragma unroll
            for (int mi = 0; mi < 2; ++mi)
#pragma unroll
                for (int ni = 0; ni < 2; ++ni)
#pragma unroll
                    for (int q = 0; q < 4; ++q)
                        acc[mi][ni][q] += RED[(hwid * 16 + (mi * 2 + ni) * 4 + q) * 32 + lane];

            // ---- Epilogue: tanh + fp16 store to ping-pong buffer ----
            int ob = (t + 1) & 1;
            __half* oh = g_h[ob];
#pragma unroll
            for (int mi = 0; mi < 2; ++mi) {
                int rA = wm * 32 + mi * 16 + (lane >> 2);
                float2 wA  = WB[rA];
                float2 wB2 = WB[rA + 8];
#pragma unroll
                for (int ni = 0; ni < 2; ++ni) {
                    int bl0 = wn * 16 + ni * 8 + 2 * (lane & 3);
                    float xb0 = XS[bl0], xb1 = XS[bl0 + 1];
                    float* a = acc[mi][ni];
                    float y00 = fast_tanh(fmaf(wA.x,  xb0, a[0] + wA.y));
                    float y01 = fast_tanh(fmaf(wA.x,  xb1, a[1] + wA.y));
                    float y10 = fast_tanh(fmaf(wB2.x, xb0, a[2] + wB2.y));
                    float y11 = fast_tanh(fmaf(wB2.x, xb1, a[3] + wB2.y));
                    size_t o0 = (size_t)(n0 + rA) * Bn + (c0 + bl0);
                    size_t o1 = o0 + (size_t)8 * Bn;
                    *(unsigned*)(oh + o0) = pack_h2(__float2half_rn(y00), __float2half_rn(y01));
                    *(unsigned*)(oh + o1) = pack_h2(__float2half_rn(y10), __float2half_rn(y11));
                }
            }
        }
        ct_barrier(ct);   // publishes this step's h within the 8-CTA group
    }

    // ---- Final projection: out[b][o] = b_y[o] + sum_k W_yh[o][k] * h[k][b] ----
    if (nt == 0) {
        float* Wy = (float*)(smem + SM_WHI);       // main loop done; reuse W region
        for (int idx = tid; idx < On * Hn; idx += 512) Wy[idx] = W_yh[idx];
        __syncthreads();
        if (tid < 64) {
            int b = c0 + tid;
            float a10[On];
#pragma unroll
            for (int o = 0; o < On; ++o) a10[o] = b_y[o];
            const __half* hh = g_h[0];
            for (int k = 0; k < Hn; ++k) {
                float hv = __half2float(hh[(size_t)k * Bn + b]);
#pragma unroll
                for (int o = 0; o < On; ++o) a10[o] = fmaf(Wy[o * Hn + k], hv, a10[o]);
            }
#pragma unroll
            for (int o = 0; o < On; ++o) out[b * On + o] = a10[o];
        }
    }
}

extern "C" void kernel_launch(void* const* d_in, const int* in_sizes, int n_in,
                              void* d_out, int out_size) {
    (void)in_sizes; (void)n_in; (void)out_size;
    const float* x    = (const float*)d_in[0];
    const float* W_hx = (const float*)d_in[1];
    const float* W_hh = (const float*)d_in[2];
    const float* W_yh = (const float*)d_in[3];
    const float* b_h  = (const float*)d_in[4];
    const float* b_y  = (const float*)d_in[5];
    float* out = (float*)d_out;

    cudaFuncSetAttribute(rnn_hmma11_kernel, cudaFuncAttributeMaxDynamicSharedMemorySize, SM_TOTAL);
    rnn_hmma11_kernel<<<NCTA, 512, SM_TOTAL>>>(x, W_hx, W_hh, W_yh, b_h, b_y, out);
}

// round 17
// speedup vs baseline: 1.9805x; 1.0864x over previous
#include <cuda_runtime.h>
#include <cuda_fp16.h>

#define Hn 512
#define Bn 1024
#define Tn 512
#define On 10
#define NCTA 128

// SMEM byte offsets
#define SM_WHI 0        // 8 chunks x [64 rows x 64 k] fp16 SW128 = 65536
#define SM_WLO 65536    // fp16 residual of W
#define SM_A   131072   // 6 bufs x 8KB (h fp16); half h owns bufs 3h..3h+2
#define SM_WB  180224   // float2[64] {W_hx, b_h}
#define SM_XS  180736   // float[64]
#define SM_TOTAL 180992

__device__ __align__(16) __half g_h[2][Hn * Bn];   // [buf][k*Bn + b], single fp16

struct alignas(128) CtBar { unsigned cnt; unsigned gen; unsigned pad[30]; };
__device__ CtBar g_ctbar[16];

static __device__ __forceinline__ unsigned smem_u32(const void* p) {
    unsigned a;
    asm("{ .reg .u64 t; cvta.to.shared.u64 t, %1; cvt.u32.u64 %0, t; }" : "=r"(a) : "l"(p));
    return a;
}
static __device__ __forceinline__ void cpa16(unsigned dst, const void* src) {
    asm volatile("cp.async.cg.shared.global [%0], [%1], 16;" :: "r"(dst), "l"(src));
}
#define CP_COMMIT() asm volatile("cp.async.commit_group;" ::: "memory")
#define CP_WAIT1()  asm volatile("cp.async.wait_group 1;" ::: "memory")
#define CP_WAIT0()  asm volatile("cp.async.wait_group 0;" ::: "memory")

static __device__ __forceinline__ void ldm4(unsigned* r, unsigned addr) {
    asm volatile("ldmatrix.sync.aligned.m8n8.x4.shared.b16 {%0,%1,%2,%3}, [%4];"
                 : "=r"(r[0]), "=r"(r[1]), "=r"(r[2]), "=r"(r[3]) : "r"(addr));
}
static __device__ __forceinline__ void ldm4t(unsigned* r, unsigned addr) {
    asm volatile("ldmatrix.sync.aligned.m8n8.x4.trans.shared.b16 {%0,%1,%2,%3}, [%4];"
                 : "=r"(r[0]), "=r"(r[1]), "=r"(r[2]), "=r"(r[3]) : "r"(addr));
}
static __device__ __forceinline__ void mma16816(float* d, const unsigned* a, const unsigned* b) {
    asm volatile("mma.sync.aligned.m16n8k16.row.col.f32.f16.f16.f32 "
                 "{%0,%1,%2,%3}, {%4,%5,%6,%7}, {%8,%9}, {%0,%1,%2,%3};"
                 : "+f"(d[0]), "+f"(d[1]), "+f"(d[2]), "+f"(d[3])
                 : "r"(a[0]), "r"(a[1]), "r"(a[2]), "r"(a[3]), "r"(b[0]), "r"(b[1]));
}

static __device__ __forceinline__ float fast_tanh(float v) {
    float e, r;
    asm("ex2.approx.f32 %0, %1;" : "=f"(e) : "f"(v * 2.885390081777927f));
    asm("rcp.approx.f32 %0, %1;" : "=f"(r) : "f"(e + 1.0f));
    return fmaf(-2.0f, r, 1.0f);
}
static __device__ __forceinline__ unsigned pack_h2(__half a, __half b) {
    return (unsigned)__half_as_ushort(a) | ((unsigned)__half_as_ushort(b) << 16);
}

// Per-half named barrier: id 1 (half 0) / id 2 (half 1), 256 threads each.
static __device__ __forceinline__ void half_bar(int half) {
    asm volatile("bar.sync %0, 256;" :: "r"(1 + half) : "memory");
}

// 8-CTA barrier over the CTAs sharing one ct group.
static __device__ __forceinline__ void ct_barrier(int ct) {
    __syncthreads();
    __threadfence();
    if (threadIdx.x == 0) {
        CtBar* cb = &g_ctbar[ct];
        unsigned gen = *((volatile unsigned*)&cb->gen);
        unsigned tkt = atomicAdd(&cb->cnt, 1u);
        if (tkt == 7u) {
            cb->cnt = 0;
            __threadfence();
            atomicAdd(&cb->gen, 1u);
        } else {
            while (*((volatile unsigned*)&cb->gen) == gen) { __nanosleep(16); }
        }
    }
    __syncthreads();
}

extern __shared__ char smem[];

__global__ void __launch_bounds__(512, 1)
rnn_hmma13_kernel(const float* __restrict__ x,    const float* __restrict__ W_hx,
                  const float* __restrict__ W_hh, const float* __restrict__ W_yh,
                  const float* __restrict__ b_h,  const float* __restrict__ b_y,
                  float* __restrict__ out)
{
    const unsigned sb = smem_u32(smem);
    const int tid  = threadIdx.x;
    const int lane = tid & 31;
    const int wid  = tid >> 5;
    const int half = wid >> 3;           // K half: 0 -> chunks 0..3, 1 -> chunks 4..7
    const int hwid = wid & 7;            // warp id within half
    const int htid = tid & 255;          // thread id within half
    const int nt   = blockIdx.x & 7;     // hidden tile 0..7
    const int ct   = blockIdx.x >> 3;    // batch group 0..15
    const int n0   = nt * 64;
    const int c0   = ct * 64;
    // warp grid within half: 4m x 2n (16-row x 32-col warp tiles)
    const int wm   = hwid & 3;           // 0..3
    const int wn   = hwid >> 2;          // 0..1

    // ---- Stage W_hh rows n0..n0+63 as fp16 hi/lo: 8 SW128 chunks [64r x 64k] ----
    for (int idx = tid; idx < 64 * Hn; idx += 512) {
        int r = idx >> 9, k = idx & 511;
        float w = W_hh[(n0 + r) * Hn + k];
        __half whi = __float2half_rn(w);
        __half wlo = __float2half_rn(w - __half2float(whi));
        int c = k >> 6, kc = k & 63;
        unsigned off = (unsigned)(r * 128 + kc * 2);
        unsigned sw  = off ^ ((off >> 3) & 0x70);
        *(__half*)(smem + SM_WHI + c * 8192 + sw) = whi;
        *(__half*)(smem + SM_WLO + c * 8192 + sw) = wlo;
    }
    if (tid < 64)
        ((float2*)(smem + SM_WB))[tid] = make_float2(W_hx[n0 + tid], b_h[n0 + tid]);

    // ---- Zero own group-aligned region of buffer 0 ----
    {
        uint4 z = make_uint4(0, 0, 0, 0);
        int r = tid >> 3, q = tid & 7;        // 512 items = 64 rows x 8 uint4
        size_t off = (size_t)(n0 + r) * Bn + c0;
        ((uint4*)(g_h[0] + off))[q] = z;
    }

    // ---- cp.async slot precompute: 2 x 16B per HALF-thread per chunk (8KB) ----
    const char* s0[2]; const char* s1[2]; unsigned dsw[2];
#pragma unroll
    for (int j = 0; j < 2; ++j) {
        int f = j * 256 + htid;          // 0..511
        int row = f >> 3, seg = f & 7;
        size_t so = (size_t)row * (Bn * 2) + seg * 16 + (size_t)c0 * 2;
        s0[j] = (const char*)g_h[0] + so;
        s1[j] = (const char*)g_h[1] + so;
        unsigned off = (unsigned)(row * 128 + seg * 16);
        dsw[j] = off ^ ((row & 7) << 4);
    }

    // ---- ldmatrix lane constants ----
    const int lane15 = lane & 15;
    const unsigned axor  = (unsigned)((lane & 7) << 4);
    const unsigned arow0 = (unsigned)((wm * 16 + lane15) * 128);   // 16-row A tile
    const unsigned acx   = ((unsigned)((lane >> 4) * 16)) ^ axor;
    const unsigned browb = (unsigned)(lane15 * 128);
    // 32-batch B tile: byte offset = wn*32 batches * 2 = wn*64 (R12-verified form)
    const unsigned bq    = ((unsigned)(wn * 64 + (lane >> 4) * 16)) ^ axor;

    const float2* WB = (const float2*)(smem + SM_WB);
    float* XS  = (float*)(smem + SM_XS);
    float* RED = (float*)(smem + SM_A);   // reduction scratch (bufs idle then)

    const int cbase = half * 4;           // first global chunk of this half
    const unsigned bufb = (unsigned)(half * 3);

    ct_barrier(ct);   // h0 zeros (group-local) + W staging visible

#define PFH(i, sp) do {                                                        \
        unsigned db = sb + SM_A + (bufb + (unsigned)((i) % 3)) * 8192u;        \
        size_t go = (size_t)(cbase + (i)) * 131072;                            \
        cpa16(db + dsw[0], (sp)[0] + go);                                      \
        cpa16(db + dsw[1], (sp)[1] + go);                                      \
        CP_COMMIT(); } while (0)

#define LDFRAG(s, ks) do {                                                     \
        unsigned colA = acx ^ (unsigned)((ks) * 32);                           \
        ldm4(ah[s], whb + arow0 + colA);                                       \
        ldm4(al[s], wlb + arow0 + colA);                                       \
        unsigned rB = hb + browb + (unsigned)((ks) * 2048);                    \
        ldm4t(bh[s],     rB + bq);                                             \
        ldm4t(bh[s] + 4, rB + (bq ^ 32u)); } while (0)

    for (int t = 0; t < Tn; ++t) {
        if (tid < 64) XS[tid] = x[(c0 + tid) * Tn + t];
        const char* const* sp = (t & 1) ? s1 : s0;
        PFH(0, sp);
        PFH(1, sp);

        float acc[4][4];
#pragma unroll
        for (int ni = 0; ni < 4; ++ni)
#pragma unroll
            for (int q = 0; q < 4; ++q) acc[ni][q] = 0.f;

        for (int i = 0; i < 4; ++i) {
            if (i < 3) CP_WAIT1(); else CP_WAIT0();
            half_bar(half);               // data visible; prior ring reads done

            const int c = cbase + i;
            const unsigned whb = sb + SM_WHI + (unsigned)(c * 8192);
            const unsigned wlb = whb + 65536;
            const unsigned hb  = sb + SM_A + (bufb + (unsigned)(i % 3)) * 8192u;

            unsigned ah[2][4], al[2][4], bh[2][8];
            LDFRAG(0, 0);
#pragma unroll
            for (int ks = 0; ks < 4; ++ks) {
                const int s = ks & 1;
                if (ks < 3) LDFRAG(s ^ 1, ks + 1);
#pragma unroll
                for (int ni = 0; ni < 4; ++ni) {
                    mma16816(acc[ni], ah[s], bh[s] + ni * 2);
                    mma16816(acc[ni], al[s], bh[s] + ni * 2);
                }
            }
            if (i < 2) PFH(i + 2, sp);    // buf (i+2)%3: last read 3 bars ago
        }

        // ---- Combine K halves: half 1 stores partials, half 0 accumulates ----
        __syncthreads();
        if (half == 1) {
#pragma unroll
            for (int ni = 0; ni < 4; ++ni)
#pragma unroll
                for (int q = 0; q < 4; ++q)
                    RED[(hwid * 16 + ni * 4 + q) * 32 + lane] = acc[ni][q];
        }
        __syncthreads();

        if (half == 0) {
#pragma unroll
            for (int ni = 0; ni < 4; ++ni)
#pragma unroll
                for (int q = 0; q < 4; ++q)
                    acc[ni][q] += RED[(hwid * 16 + ni * 4 + q) * 32 + lane];

            // ---- Epilogue: tanh + fp16 store to ping-pong buffer ----
            int ob = (t + 1) & 1;
            __half* oh = g_h[ob];
            int rA = wm * 16 + (lane >> 2);
            float2 wA  = WB[rA];
            float2 wB2 = WB[rA + 8];
#pragma unroll
            for (int ni = 0; ni < 4; ++ni) {
                int bl0 = wn * 32 + ni * 8 + 2 * (lane & 3);
                float xb0 = XS[bl0], xb1 = XS[bl0 + 1];
                float* a = acc[ni];
                float y00 = fast_tanh(fmaf(wA.x,  xb0, a[0] + wA.y));
                float y01 = fast_tanh(fmaf(wA.x,  xb1, a[1] + wA.y));
                float y10 = fast_tanh(fmaf(wB2.x, xb0, a[2] + wB2.y));
                float y11 = fast_tanh(fmaf(wB2.x, xb1, a[3] + wB2.y));
                size_t o0 = (size_t)(n0 + rA) * Bn + (c0 + bl0);
                size_t o1 = o0 + (size_t)8 * Bn;
                *(unsigned*)(oh + o0) = pack_h2(__float2half_rn(y00), __float2half_rn(y01));
                *(unsigned*)(oh + o1) = pack_h2(__float2half_rn(y10), __float2half_rn(y11));
            }
        }
        ct_barrier(ct);   // publishes this step's h within the 8-CTA group
    }

    // ---- Final projection: out[b][o] = b_y[o] + sum_k W_yh[o][k] * h[k][b] ----
    if (nt == 0) {
        float* Wy = (float*)(smem + SM_WHI);       // main loop done; reuse W region
        for (int idx = tid; idx < On * Hn; idx += 512) Wy[idx] = W_yh[idx];
        __syncthreads();
        if (tid < 64) {
            int b = c0 + tid;
            float a10[On];
#pragma unroll
            for (int o = 0; o < On; ++o) a10[o] = b_y[o];
            const __half* hh = g_h[0];
            for (int k = 0; k < Hn; ++k) {
                float hv = __half2float(hh[(size_t)k * Bn + b]);
#pragma unroll
                for (int o = 0; o < On; ++o) a10[o] = fmaf(Wy[o * Hn + k], hv, a10[o]);
            }
#pragma unroll
            for (int o = 0; o < On; ++o) out[b * On + o] = a10[o];
        }
    }
}

extern "C" void kernel_launch(void* const* d_in, const int* in_sizes, int n_in,
                              void* d_out, int out_size) {
    (void)in_sizes; (void)n_in; (void)out_size;
    const float* x    = (const float*)d_in[0];
    const float* W_hx = (const float*)d_in[1];
    const float* W_hh = (const float*)d_in[2];
    const float* W_yh = (const float*)d_in[3];
    const float* b_h  = (const float*)d_in[4];
    const float* b_y  = (const float*)d_in[5];
    float* out = (float*)d_out;

    cudaFuncSetAttribute(rnn_hmma13_kernel, cudaFuncAttributeMaxDynamicSharedMemorySize, SM_TOTAL);
    rnn_hmma13_kernel<<<NCTA, 512, SM_TOTAL>>>(x, W_hx, W_hh, W_yh, b_h, b_y, out);
}